// round 5
// baseline (speedup 1.0000x reference)
#include <cuda_runtime.h>
#include <cuda_bf16.h>
#include <math.h>
#include <stdint.h>

#define BATCH 512
#define SEQ   196
#define HID   1024
#define MID   512
#define FOUT  2048
#define NB    100
#define ROWS  (BATCH*SEQ)      // 100352
#define CHUNK_ROWS 25088       // ROWS/4 = 128 batches = 196 row tiles
#define CHUNK_F4   6422528     // CHUNK_ROWS*HID/4

__device__ __align__(16) float g_att[ROWS];
__device__ __align__(16) float g_ctx[BATCH*HID];
__device__ __align__(16) __nv_bfloat16 g_w1b[MID*HID];
__device__ __align__(16) __nv_bfloat16 g_xb[(size_t)ROWS*HID];

__device__ __forceinline__ unsigned pack_bf16(float lo, float hi) {
    unsigned r; asm("cvt.rn.bf16x2.f32 %0, %1, %2;" : "=r"(r) : "f"(hi), "f"(lo)); return r;
}
__device__ __forceinline__ unsigned f2tf32(float x) {
    unsigned y; asm("cvt.rna.tf32.f32 %0, %1;" : "=r"(y) : "f"(x)); return y;
}
__device__ __forceinline__ uint32_t smem_u32(const void* p) {
    uint32_t a;
    asm("{ .reg .u64 t; cvta.to.shared.u64 t, %1; cvt.u32.u64 %0, t; }" : "=r"(a) : "l"(p));
    return a;
}

#define SWZ64(o) ((o) ^ (((o) >> 3) & 0x30))
#define CP16(dst, src) \
    asm volatile("cp.async.cg.shared.global [%0], [%1], 16;" :: "r"(dst), "l"(src) : "memory")
#define CP_COMMIT() asm volatile("cp.async.commit_group;" ::: "memory")
#define CP_WAIT2()  asm volatile("cp.async.wait_group 2;" ::: "memory")
#define LDSM_X4(r0, r1, r2, r3, addr) \
    asm volatile("ldmatrix.sync.aligned.m8n8.x4.shared.b16 {%0,%1,%2,%3}, [%4];" \
                 : "=r"(r0), "=r"(r1), "=r"(r2), "=r"(r3) : "r"(addr))
#define MMA_BF16(d, a0, a1, a2, a3, b0, b1) \
    asm volatile("mma.sync.aligned.m16n8k16.row.col.f32.bf16.bf16.f32 " \
                 "{%0,%1,%2,%3},{%4,%5,%6,%7},{%8,%9},{%0,%1,%2,%3};" \
                 : "+f"((d)[0]), "+f"((d)[1]), "+f"((d)[2]), "+f"((d)[3]) \
                 : "r"(a0), "r"(a1), "r"(a2), "r"(a3), "r"(b0), "r"(b1))

// ===========================================================================
// k_pre: cvt x chunk0 -> bf16, cvt W1 -> bf16, zero g_att
// ===========================================================================
__global__ void k_pre(const float* __restrict__ x, const float* __restrict__ W1) {
    size_t i = (size_t)blockIdx.x * 256 + threadIdx.x;
    if (i < CHUNK_F4) {
        float4 v = ((const float4*)x)[i];
        ((uint2*)g_xb)[i] = make_uint2(pack_bf16(v.x, v.y), pack_bf16(v.z, v.w));
    } else if (i < CHUNK_F4 + 131072) {
        size_t j = i - CHUNK_F4;
        float4 v = ((const float4*)W1)[j];
        ((uint2*)g_w1b)[j] = make_uint2(pack_bf16(v.x, v.y), pack_bf16(v.z, v.w));
    } else {
        size_t j = i - (CHUNK_F4 + 131072);
        ((float4*)g_att)[j] = make_float4(0.f, 0.f, 0.f, 0.f);
    }
}

// ===========================================================================
// k_mlp_att: bf16 GEMM (BM=128,BN=128,BK=32), 4-stage cp.async, 4 warps,
//   64x64 warp tiles, fused relu/W2 row-sum -> atomicAdd g_att.
//   Also converts next chunk's x fp32->bf16 (hidden under MMA).
// ===========================================================================
#define NKT 32
#define GEMM_SMEM (65536 + 1024)

__global__ __launch_bounds__(128, 2)
void k_mlp_att(const float* __restrict__ b1,
               const float* __restrict__ W2,
               const float* __restrict__ x,
               int chunk) {
    extern __shared__ char raw[];
    char* smem = (char*)(((uintptr_t)raw + 1023) & ~(uintptr_t)1023);
    const uint32_t sbase = smem_u32(smem);       // A: +s*8192, B: +32768+s*8192
    __shared__ float b1s[128], w2s[128], s_part[128];

    const int tid  = threadIdx.x;
    const int lane = tid & 31;
    const int warp = tid >> 5;
    const int colBase = blockIdx.x * 128;
    const int rowBase = chunk * CHUNK_ROWS + blockIdx.y * 128;

    b1s[tid] = b1[colBase + tid];
    w2s[tid] = W2[colBase + tid];
    s_part[tid] = 0.f;

    // next-chunk conversion task
    const int  flat  = blockIdx.y * 4 + blockIdx.x;     // 0..783
    const bool doCvt = (chunk < 3);
    const float4* cvtSrc = ((const float4*)x) + (size_t)(chunk + 1) * CHUNK_F4 + (size_t)flat * 8192;
    uint2*        cvtDst = ((uint2*)g_xb)     + (size_t)(chunk + 1) * CHUNK_F4 + (size_t)flat * 8192;

    // warp tiling: 2x2 warps, 64x64 each
    const int wm = warp & 1, wn = warp >> 1;
    const int mBase = wm * 64, nBase = wn * 64;
    const int g = lane >> 2, t = lane & 3;

    const int aRow = mBase + (lane & 15);
    const int aKb  = (lane >> 4) * 16;
    const int bRow = nBase + (lane & 7) + ((lane >> 4) * 8);
    const int bKb  = ((lane >> 3) & 1) * 16;

    uint32_t aOff[4][2], bOff[4][2];
    #pragma unroll
    for (int mi = 0; mi < 4; mi++)
        #pragma unroll
        for (int ks = 0; ks < 2; ks++)
            aOff[mi][ks] = SWZ64((uint32_t)((aRow + mi * 16) * 64 + ks * 32 + aKb));
    #pragma unroll
    for (int nj = 0; nj < 4; nj++)
        #pragma unroll
        for (int ks = 0; ks < 2; ks++)
            bOff[nj][ks] = SWZ64((uint32_t)((bRow + nj * 16) * 64 + ks * 32 + bKb));

    // cp.async addressing: thread -> row tid, 4x16B chunks per tile
    uint32_t dstOff[4];
    #pragma unroll
    for (int c = 0; c < 4; c++) dstOff[c] = SWZ64((uint32_t)(tid * 64 + c * 16));
    const __nv_bfloat16* srcA = g_xb  + (size_t)(rowBase + tid) * HID;
    const __nv_bfloat16* srcB = g_w1b + (size_t)(colBase + tid) * HID;

    float acc[4][8][4];
    #pragma unroll
    for (int mi = 0; mi < 4; mi++)
        #pragma unroll
        for (int ni = 0; ni < 8; ni++)
            #pragma unroll
            for (int q = 0; q < 4; q++) acc[mi][ni][q] = 0.f;

    // prologue: stages 0..2
    #pragma unroll
    for (int s = 0; s < 3; ++s) {
        const uint32_t ab = sbase + s * 8192;
        const uint32_t bb = sbase + 32768 + s * 8192;
        #pragma unroll
        for (int c = 0; c < 4; c++) CP16(ab + dstOff[c], srcA + s * 32 + c * 8);
        #pragma unroll
        for (int c = 0; c < 4; c++) CP16(bb + dstOff[c], srcB + s * 32 + c * 8);
        CP_COMMIT();
    }

    for (int kt = 0; kt < NKT; ++kt) {
        CP_WAIT2();
        __syncthreads();

        if (kt + 3 < NKT) {
            const int s = (kt + 3) & 3;
            const uint32_t ab = sbase + s * 8192;
            const uint32_t bb = sbase + 32768 + s * 8192;
            #pragma unroll
            for (int c = 0; c < 4; c++) CP16(ab + dstOff[c], srcA + (kt + 3) * 32 + c * 8);
            #pragma unroll
            for (int c = 0; c < 4; c++) CP16(bb + dstOff[c], srcB + (kt + 3) * 32 + c * 8);
        }
        CP_COMMIT();

        float4 cv0, cv1;
        if (doCvt) { cv0 = cvtSrc[kt * 256 + tid]; cv1 = cvtSrc[kt * 256 + 128 + tid]; }

        const uint32_t aBase = sbase + (kt & 3) * 8192;
        const uint32_t bBase = sbase + 32768 + (kt & 3) * 8192;
        #pragma unroll
        for (int ks = 0; ks < 2; ++ks) {
            uint32_t a[4][4];
            #pragma unroll
            for (int mi = 0; mi < 4; mi++)
                LDSM_X4(a[mi][0], a[mi][1], a[mi][2], a[mi][3], aBase + aOff[mi][ks]);
            #pragma unroll
            for (int nj = 0; nj < 4; nj++) {
                uint32_t b0, b1r, b2, b3;
                LDSM_X4(b0, b1r, b2, b3, bBase + bOff[nj][ks]);
                #pragma unroll
                for (int mi = 0; mi < 4; mi++) {
                    MMA_BF16(acc[mi][nj * 2],     a[mi][0], a[mi][1], a[mi][2], a[mi][3], b0, b1r);
                    MMA_BF16(acc[mi][nj * 2 + 1], a[mi][0], a[mi][1], a[mi][2], a[mi][3], b2, b3);
                }
            }
        }

        if (doCvt) {
            cvtDst[kt * 256 + tid]       = make_uint2(pack_bf16(cv0.x, cv0.y), pack_bf16(cv0.z, cv0.w));
            cvtDst[kt * 256 + 128 + tid] = make_uint2(pack_bf16(cv1.x, cv1.y), pack_bf16(cv1.z, cv1.w));
        }
    }

    // epilogue: relu(acc+b1)*W2, reduce over this CTA's 128 cols
    #pragma unroll
    for (int mi = 0; mi < 4; mi++) {
        float s0 = 0.f, s1 = 0.f;
        #pragma unroll
        for (int ni = 0; ni < 8; ni++) {
            int c = nBase + ni * 8 + t * 2;
            s0 += fmaxf(acc[mi][ni][0] + b1s[c],     0.f) * w2s[c]
                + fmaxf(acc[mi][ni][1] + b1s[c + 1], 0.f) * w2s[c + 1];
            s1 += fmaxf(acc[mi][ni][2] + b1s[c],     0.f) * w2s[c]
                + fmaxf(acc[mi][ni][3] + b1s[c + 1], 0.f) * w2s[c + 1];
        }
        s0 += __shfl_xor_sync(0xffffffff, s0, 1); s0 += __shfl_xor_sync(0xffffffff, s0, 2);
        s1 += __shfl_xor_sync(0xffffffff, s1, 1); s1 += __shfl_xor_sync(0xffffffff, s1, 2);
        if (t == 0) {
            atomicAdd(&s_part[mBase + mi * 16 + g],     s0);
            atomicAdd(&s_part[mBase + mi * 16 + 8 + g], s1);
        }
    }
    __syncthreads();
    atomicAdd(&g_att[rowBase + tid], s_part[tid]);
}

// ===========================================================================
// k_stats4: per-batch softmax/moments/r/w, then h-sliced context stream.
//   grid (4 slices, 512 batches), 256 threads.
// ===========================================================================
__global__ __launch_bounds__(256)
void k_stats4(const float* __restrict__ x,
              const unsigned char* __restrict__ mask,
              const float* __restrict__ G,
              const float* __restrict__ mub) {
    __shared__ float smax[8], ssum[8][6];
    __shared__ float r_s[NB], w_s[SEQ];
    __shared__ float4 red[256];

    const int b = blockIdx.y, slice = blockIdx.x;
    const int tid = threadIdx.x, lane = tid & 31, warp = tid >> 5;

    float logit = -3.0e38f;
    if (tid < SEQ) {
        logit = g_att[b * SEQ + tid];
        if (mask[b * SEQ + tid]) logit = -1.0e9f;
    }
    float v = logit;
    #pragma unroll
    for (int off = 16; off > 0; off >>= 1) v = fmaxf(v, __shfl_xor_sync(0xffffffff, v, off));
    if (lane == 0) smax[warp] = v;
    __syncthreads();
    float mx = smax[0];
    #pragma unroll
    for (int w = 1; w < 8; w++) mx = fmaxf(mx, smax[w]);

    float e = (tid < SEQ) ? expf(logit - mx) : 0.f;
    float px = 0.f, py = 0.f;
    if (tid < SEQ) { px = (float)(tid / 14) * (1.f / 13.f); py = (float)(tid % 14) * (1.f / 13.f); }
    float s6[6] = { e, e * px, e * py, e * px * px, e * px * py, e * py * py };
    #pragma unroll
    for (int q = 0; q < 6; q++) {
        float sv = s6[q];
        #pragma unroll
        for (int off = 16; off > 0; off >>= 1) sv += __shfl_xor_sync(0xffffffff, sv, off);
        if (lane == 0) ssum[warp][q] = sv;
        s6[q] = sv;
    }
    __syncthreads();
    float sums[6];
    #pragma unroll
    for (int q = 0; q < 6; q++) {
        float sv = 0.f;
        #pragma unroll
        for (int w = 0; w < 8; w++) sv += ssum[w][q];
        sums[q] = sv;
    }

    const float S   = sums[0];
    const float Mux = sums[1] / S, Muy = sums[2] / S;
    float S00 = sums[3] / S - Mux * Mux + 1e-6f;
    float S01 = sums[4] / S - Mux * Muy;
    float S11 = sums[5] / S - Muy * Muy + 1e-6f;
    float det = S00 * S11 - S01 * S01;
    float I00 = S11 / det, I01 = -S01 / det, I11 = S00 / det;
    float t0 = I00 * Mux + I01 * Muy;
    float t1 = I01 * Mux + I11 * Muy;
    float ds = I00 * I11 - I01 * I01;
    float R00 = I11 / ds, R01 = -I01 / ds, R11 = I00 / ds;
    float m0 = R00 * t0 + R01 * t1;
    float m1 = R01 * t0 + R11 * t1;
    float A00 = R00 + 1e-3f, A01 = R01, A11 = R11 + 1e-3f;
    float detA = A00 * A11 - A01 * A01;
    float Ai00 = A11 / detA, Ai01 = -A01 / detA, Ai11 = A00 / detA;
    float coef = 1.f / (6.2831853071795864769f * sqrtf(detA));

    if (tid < NB) {
        float d0 = m0 - mub[2 * tid];
        float d1 = m1 - mub[2 * tid + 1];
        float quad = d0 * (Ai00 * d0 + Ai01 * d1) + d1 * (Ai01 * d0 + Ai11 * d1);
        r_s[tid] = expf(-0.5f * quad) * coef;
    }
    __syncthreads();
    if (tid < SEQ) {
        float wv = 0.f;
        #pragma unroll 4
        for (int k = 0; k < NB; k++) wv += G[tid * NB + k] * r_s[k];
        w_s[tid] = wv;
    }
    __syncthreads();

    // context slice: h in [slice*256, slice*256+256)
    const int h4 = tid & 63, nn = tid >> 6;
    const float4* xb = (const float4*)(x + (size_t)b * SEQ * HID) + slice * 64 + h4;
    float ax = 0.f, ay = 0.f, az = 0.f, aw = 0.f;
    #pragma unroll 7
    for (int n = nn; n < SEQ; n += 4) {
        float4 vv = xb[n * 256];
        float wv = w_s[n];
        ax += wv * vv.x; ay += wv * vv.y; az += wv * vv.z; aw += wv * vv.w;
    }
    red[tid] = make_float4(ax, ay, az, aw);
    __syncthreads();
    if (tid < 64) {
        float4 a0 = red[tid], a1 = red[tid + 64], a2 = red[tid + 128], a3 = red[tid + 192];
        float4 o;
        o.x = a0.x + a1.x + a2.x + a3.x;
        o.y = a0.y + a1.y + a2.y + a3.y;
        o.z = a0.z + a1.z + a2.z + a3.z;
        o.w = a0.w + a1.w + a2.w + a3.w;
        ((float4*)(g_ctx + (size_t)b * HID + slice * 256))[tid] = o;
    }
}

// ===========================================================================
// k_out2: out = ctx(512x1024) @ Wm^T + bm  (tf32 mma.sync, BM=64 BN=128)
// ===========================================================================
#define BM2 64
#define BN2 128
#define XS2 20

__global__ __launch_bounds__(256, 2)
void k_out2(const float* __restrict__ Wm, const float* __restrict__ bm,
            float* __restrict__ out) {
    __shared__ unsigned sa[2][BM2][XS2];
    __shared__ unsigned sbm[2][BN2][XS2];

    const int tid = threadIdx.x;
    const int mB = blockIdx.x * BM2, nB = blockIdx.y * BN2;
    const int lr = tid >> 2, lc = (tid & 3) * 4;
    const int warp = tid >> 5, lane = tid & 31;
    const int wm = warp & 1, wn = warp >> 1;
    const int mBase = wm * 32, nBase = wn * 32;
    const int g = lane >> 2, t = lane & 3;

    float acc[2][4][4];
    #pragma unroll
    for (int mi = 0; mi < 2; mi++)
        #pragma unroll
        for (int ni = 0; ni < 4; ni++)
            #pragma unroll
            for (int q = 0; q < 4; q++) acc[mi][ni][q] = 0.f;

    float4 pa, pb0, pb1;
    pa  = *(const float4*)&g_ctx[(size_t)(mB + lr) * HID + lc];
    pb0 = *(const float4*)&Wm  [(size_t)(nB + lr) * HID + lc];
    pb1 = *(const float4*)&Wm  [(size_t)(nB + lr + 64) * HID + lc];
    sa [0][lr][lc+0] = f2tf32(pa.x);  sa [0][lr][lc+1] = f2tf32(pa.y);
    sa [0][lr][lc+2] = f2tf32(pa.z);  sa [0][lr][lc+3] = f2tf32(pa.w);
    sbm[0][lr][lc+0] = f2tf32(pb0.x); sbm[0][lr][lc+1] = f2tf32(pb0.y);
    sbm[0][lr][lc+2] = f2tf32(pb0.z); sbm[0][lr][lc+3] = f2tf32(pb0.w);
    sbm[0][lr+64][lc+0] = f2tf32(pb1.x); sbm[0][lr+64][lc+1] = f2tf32(pb1.y);
    sbm[0][lr+64][lc+2] = f2tf32(pb1.z); sbm[0][lr+64][lc+3] = f2tf32(pb1.w);
    __syncthreads();

    const int NT = HID / 16;
    for (int kt = 0; kt < NT; ++kt) {
        const int buf = kt & 1;
        if (kt < NT - 1) {
            int k0 = (kt + 1) * 16;
            pa  = *(const float4*)&g_ctx[(size_t)(mB + lr) * HID + k0 + lc];
            pb0 = *(const float4*)&Wm  [(size_t)(nB + lr) * HID + k0 + lc];
            pb1 = *(const float4*)&Wm  [(size_t)(nB + lr + 64) * HID + k0 + lc];
        }
        #pragma unroll
        for (int ks = 0; ks < 2; ++ks) {
            const int k0s = ks * 8;
            unsigned a[2][4], bf[4][2];
            #pragma unroll
            for (int mi = 0; mi < 2; mi++) {
                int r0 = mBase + mi * 16 + g;
                a[mi][0] = sa[buf][r0    ][k0s + t];
                a[mi][1] = sa[buf][r0 + 8][k0s + t];
                a[mi][2] = sa[buf][r0    ][k0s + t + 4];
                a[mi][3] = sa[buf][r0 + 8][k0s + t + 4];
            }
            #pragma unroll
            for (int ni = 0; ni < 4; ni++) {
                int c0 = nBase + ni * 8 + g;
                bf[ni][0] = sbm[buf][c0][k0s + t];
                bf[ni][1] = sbm[buf][c0][k0s + t + 4];
            }
            #pragma unroll
            for (int mi = 0; mi < 2; mi++)
                #pragma unroll
                for (int ni = 0; ni < 4; ni++)
                    asm volatile(
                        "mma.sync.aligned.m16n8k8.row.col.f32.tf32.tf32.f32 "
                        "{%0,%1,%2,%3},{%4,%5,%6,%7},{%8,%9},{%0,%1,%2,%3};"
                        : "+f"(acc[mi][ni][0]), "+f"(acc[mi][ni][1]),
                          "+f"(acc[mi][ni][2]), "+f"(acc[mi][ni][3])
                        : "r"(a[mi][0]), "r"(a[mi][1]), "r"(a[mi][2]), "r"(a[mi][3]),
                          "r"(bf[ni][0]), "r"(bf[ni][1]));
        }
        if (kt < NT - 1) {
            int nb = buf ^ 1;
            sa [nb][lr][lc+0] = f2tf32(pa.x);  sa [nb][lr][lc+1] = f2tf32(pa.y);
            sa [nb][lr][lc+2] = f2tf32(pa.z);  sa [nb][lr][lc+3] = f2tf32(pa.w);
            sbm[nb][lr][lc+0] = f2tf32(pb0.x); sbm[nb][lr][lc+1] = f2tf32(pb0.y);
            sbm[nb][lr][lc+2] = f2tf32(pb0.z); sbm[nb][lr][lc+3] = f2tf32(pb0.w);
            sbm[nb][lr+64][lc+0] = f2tf32(pb1.x); sbm[nb][lr+64][lc+1] = f2tf32(pb1.y);
            sbm[nb][lr+64][lc+2] = f2tf32(pb1.z); sbm[nb][lr+64][lc+3] = f2tf32(pb1.w);
        }
        __syncthreads();
    }

    #pragma unroll
    for (int mi = 0; mi < 2; mi++)
        #pragma unroll
        for (int ni = 0; ni < 4; ni++) {
            int r0 = mB + mBase + mi * 16 + g;
            int c0 = nB + nBase + ni * 8 + t * 2;
            float bm0 = bm[c0], bm1 = bm[c0 + 1];
            out[(size_t)r0 * FOUT + c0]           = acc[mi][ni][0] + bm0;
            out[(size_t)r0 * FOUT + c0 + 1]       = acc[mi][ni][1] + bm1;
            out[(size_t)(r0 + 8) * FOUT + c0]     = acc[mi][ni][2] + bm0;
            out[(size_t)(r0 + 8) * FOUT + c0 + 1] = acc[mi][ni][3] + bm1;
        }
}

// ---------------------------------------------------------------------------
extern "C" void kernel_launch(void* const* d_in, const int* in_sizes, int n_in,
                              void* d_out, int out_size) {
    const float*         x   = (const float*)d_in[0];
    const unsigned char* xm  = (const unsigned char*)d_in[1];
    const float*         W1  = (const float*)d_in[2];
    const float*         b1  = (const float*)d_in[3];
    const float*         W2  = (const float*)d_in[4];
    // d_in[5] = b2: softmax-invariant
    const float*         Wm  = (const float*)d_in[6];
    const float*         bm  = (const float*)d_in[7];
    const float*         G   = (const float*)d_in[8];
    const float*         mub = (const float*)d_in[9];
    float* out = (float*)d_out;

    cudaFuncSetAttribute(k_mlp_att, cudaFuncAttributeMaxDynamicSharedMemorySize, GEMM_SMEM);

    k_pre<<<25698, 256>>>(x, W1);
    for (int c = 0; c < 4; ++c)
        k_mlp_att<<<dim3(4, 196), 128, GEMM_SMEM>>>(b1, W2, x, c);
    k_stats4<<<dim3(4, BATCH), 256>>>(x, xm, G, mub);
    k_out2<<<dim3(BATCH / BM2, FOUT / BN2), 256>>>(Wm, bm, out);
}

// round 6
// speedup vs baseline: 1.2558x; 1.2558x over previous
#include <cuda_runtime.h>
#include <cuda_bf16.h>
#include <math.h>
#include <stdint.h>

#define BATCH 512
#define SEQ   196
#define HID   1024
#define MID   512
#define FOUT  2048
#define NB    100
#define ROWS  (BATCH*SEQ)      // 100352

__device__ __align__(16) float g_att[ROWS];
__device__ __align__(16) float g_ctx[BATCH*HID];
__device__ __align__(16) __nv_bfloat16 g_w1b[MID*HID];

__device__ __forceinline__ unsigned pack_bf16(float lo, float hi) {
    unsigned r; asm("cvt.rn.bf16x2.f32 %0, %1, %2;" : "=r"(r) : "f"(hi), "f"(lo)); return r;
}
__device__ __forceinline__ unsigned f2tf32(float x) {
    unsigned y; asm("cvt.rna.tf32.f32 %0, %1;" : "=r"(y) : "f"(x)); return y;
}
__device__ __forceinline__ uint32_t smem_u32(const void* p) {
    uint32_t a;
    asm("{ .reg .u64 t; cvta.to.shared.u64 t, %1; cvt.u32.u64 %0, t; }" : "=r"(a) : "l"(p));
    return a;
}

#define SWZ64(o) ((o) ^ (((o) >> 3) & 0x30))
#define CP16(dst, src) \
    asm volatile("cp.async.cg.shared.global [%0], [%1], 16;" :: "r"(dst), "l"(src) : "memory")
#define CP_COMMIT() asm volatile("cp.async.commit_group;" ::: "memory")
#define CP_WAIT2()  asm volatile("cp.async.wait_group 2;" ::: "memory")
#define STS128U(addr, r0, r1, r2, r3) \
    asm volatile("st.shared.v4.b32 [%0], {%1,%2,%3,%4};" \
                 :: "r"(addr), "r"(r0), "r"(r1), "r"(r2), "r"(r3) : "memory")
#define LDSM_X4(r0, r1, r2, r3, addr) \
    asm volatile("ldmatrix.sync.aligned.m8n8.x4.shared.b16 {%0,%1,%2,%3}, [%4];" \
                 : "=r"(r0), "=r"(r1), "=r"(r2), "=r"(r3) : "r"(addr))
#define MMA_BF16(d, a0, a1, a2, a3, b0, b1) \
    asm volatile("mma.sync.aligned.m16n8k16.row.col.f32.bf16.bf16.f32 " \
                 "{%0,%1,%2,%3},{%4,%5,%6,%7},{%8,%9},{%0,%1,%2,%3};" \
                 : "+f"((d)[0]), "+f"((d)[1]), "+f"((d)[2]), "+f"((d)[3]) \
                 : "r"(a0), "r"(a1), "r"(a2), "r"(a3), "r"(b0), "r"(b1))

// ===========================================================================
// k_pre: cvt W1 -> bf16 (1MB), zero g_att
// ===========================================================================
__global__ void k_pre(const float* __restrict__ W1) {
    size_t i = (size_t)blockIdx.x * 256 + threadIdx.x;
    if (i < 131072) {
        float4 v = ((const float4*)W1)[i];
        ((uint2*)g_w1b)[i] = make_uint2(pack_bf16(v.x, v.y), pack_bf16(v.z, v.w));
    } else {
        ((float4*)g_att)[i - 131072] = make_float4(0.f, 0.f, 0.f, 0.f);
    }
}

// ===========================================================================
// k_mlp_att: bf16 mma.sync GEMM, BM=128 x BN=256, BK=32, 8 warps (64x64 tiles)
//   A: x fp32 LDG -> cvt -> STS, double-buffered.  B: W1 bf16, 4-stage cp.async.
//   Fused relu/W2 row-sum epilogue -> atomicAdd g_att. 1 CTA/SM.
// ===========================================================================
#define NKT 32
#define OFF_A(s)  ((s) * 8192)                  // 128 rows * 64B, 2 stages
#define OFF_B(s)  (16384 + (s) * 16384)         // 256 rows * 64B, 4 stages
#define OFF_SC    81920
#define GEMM_SMEM (OFF_SC + 2560)

__global__ __launch_bounds__(256, 1)
void k_mlp_att(const float* __restrict__ x,
               const float* __restrict__ b1,
               const float* __restrict__ W2) {
    extern __shared__ __align__(1024) char smem[];
    const uint32_t sbase = smem_u32(smem);

    const int tid  = threadIdx.x;
    const int lane = tid & 31;
    const int warp = tid >> 5;
    const int colBase = blockIdx.x * 256;     // n tile (2 tiles), fastest-varying
    const int rowBase = blockIdx.y * 128;

    float* b1s    = (float*)(smem + OFF_SC);
    float* w2s    = (float*)(smem + OFF_SC + 1024);
    float* s_part = (float*)(smem + OFF_SC + 2048);

    b1s[tid] = b1[colBase + tid];
    w2s[tid] = W2[colBase + tid];
    if (tid < 128) s_part[tid] = 0.f;

    // warp tiling: 2 m-warps x 4 n-warps, 64x64 each
    const int wm = warp & 1, wn = warp >> 1;
    const int mBase = wm * 64, nBase = wn * 64;
    const int g = lane >> 2, t = lane & 3;

    const int aRow = mBase + (lane & 15);
    const int aKb  = (lane >> 4) * 16;
    const int bRow = nBase + (lane & 7) + ((lane >> 4) * 8);
    const int bKb  = ((lane >> 3) & 1) * 16;

    uint32_t aOff[4][2], bOff[4][2];
    #pragma unroll
    for (int mi = 0; mi < 4; mi++)
        #pragma unroll
        for (int ks = 0; ks < 2; ks++)
            aOff[mi][ks] = SWZ64((uint32_t)((aRow + mi * 16) * 64 + ks * 32 + aKb));
    #pragma unroll
    for (int nj = 0; nj < 4; nj++)
        #pragma unroll
        for (int ks = 0; ks < 2; ks++)
            bOff[nj][ks] = SWZ64((uint32_t)((bRow + nj * 16) * 64 + ks * 32 + bKb));

    // A staging: row = tid>>1 (0..127), 16 floats at col (tid&1)*16
    const int arow = tid >> 1;
    const int ac16 = (tid & 1) * 16;
    const float* aSrc = x + (size_t)(rowBase + arow) * HID + ac16;
    const uint32_t aO0 = SWZ64((uint32_t)(arow * 64 + ac16 * 2));
    const uint32_t aO1 = SWZ64((uint32_t)(arow * 64 + ac16 * 2 + 16));

    // B cp.async: row = tid (0..255), 4x16B
    const __nv_bfloat16* bSrc = g_w1b + (size_t)(colBase + tid) * HID;
    uint32_t bDst[4];
    #pragma unroll
    for (int c = 0; c < 4; c++) bDst[c] = SWZ64((uint32_t)(tid * 64 + c * 16));

    float acc[4][8][4];
    #pragma unroll
    for (int mi = 0; mi < 4; mi++)
        #pragma unroll
        for (int ni = 0; ni < 8; ni++)
            #pragma unroll
            for (int q = 0; q < 4; q++) acc[mi][ni][q] = 0.f;

    // ---- prologue: B stages 0..2, A stage 0 ----
    #pragma unroll
    for (int s = 0; s < 3; ++s) {
        const uint32_t bb = sbase + OFF_B(s);
        #pragma unroll
        for (int c = 0; c < 4; c++) CP16(bb + bDst[c], bSrc + s * 32 + c * 8);
        CP_COMMIT();
    }
    {
        float4 f0 = *(const float4*)(aSrc);
        float4 f1 = *(const float4*)(aSrc + 4);
        float4 f2 = *(const float4*)(aSrc + 8);
        float4 f3 = *(const float4*)(aSrc + 12);
        STS128U(sbase + OFF_A(0) + aO0, pack_bf16(f0.x, f0.y), pack_bf16(f0.z, f0.w),
                                        pack_bf16(f1.x, f1.y), pack_bf16(f1.z, f1.w));
        STS128U(sbase + OFF_A(0) + aO1, pack_bf16(f2.x, f2.y), pack_bf16(f2.z, f2.w),
                                        pack_bf16(f3.x, f3.y), pack_bf16(f3.z, f3.w));
    }

    for (int kt = 0; kt < NKT; ++kt) {
        float4 f0, f1, f2, f3;
        if (kt < NKT - 1) {
            const float* p = aSrc + (kt + 1) * 32;
            f0 = *(const float4*)(p);
            f1 = *(const float4*)(p + 4);
            f2 = *(const float4*)(p + 8);
            f3 = *(const float4*)(p + 12);
        }

        CP_WAIT2();            // B stage kt complete (2 stages in flight)
        __syncthreads();       // stage kt + A[kt&1] visible to all; prior reads done

        // issue B stage kt+3 (overwrites stage (kt-1)&3, safely past the barrier)
        if (kt + 3 < NKT) {
            const uint32_t bb = sbase + OFF_B((kt + 3) & 3);
            #pragma unroll
            for (int c = 0; c < 4; c++) CP16(bb + bDst[c], bSrc + (kt + 3) * 32 + c * 8);
        }
        CP_COMMIT();

        const uint32_t aBase = sbase + OFF_A(kt & 1);
        const uint32_t bBase = sbase + OFF_B(kt & 3);
        #pragma unroll
        for (int ks = 0; ks < 2; ++ks) {
            uint32_t a[4][4];
            #pragma unroll
            for (int mi = 0; mi < 4; mi++)
                LDSM_X4(a[mi][0], a[mi][1], a[mi][2], a[mi][3], aBase + aOff[mi][ks]);
            #pragma unroll
            for (int nj = 0; nj < 4; nj++) {
                uint32_t b0, b1r, b2, b3;
                LDSM_X4(b0, b1r, b2, b3, bBase + bOff[nj][ks]);
                #pragma unroll
                for (int mi = 0; mi < 4; mi++) {
                    MMA_BF16(acc[mi][nj * 2],     a[mi][0], a[mi][1], a[mi][2], a[mi][3], b0, b1r);
                    MMA_BF16(acc[mi][nj * 2 + 1], a[mi][0], a[mi][1], a[mi][2], a[mi][3], b2, b3);
                }
            }
        }

        if (kt < NKT - 1) {
            const uint32_t ab = sbase + OFF_A((kt + 1) & 1);
            STS128U(ab + aO0, pack_bf16(f0.x, f0.y), pack_bf16(f0.z, f0.w),
                              pack_bf16(f1.x, f1.y), pack_bf16(f1.z, f1.w));
            STS128U(ab + aO1, pack_bf16(f2.x, f2.y), pack_bf16(f2.z, f2.w),
                              pack_bf16(f3.x, f3.y), pack_bf16(f3.z, f3.w));
        }
    }

    // epilogue: relu(acc+b1)*W2 row-sum over this CTA's 256 cols
    #pragma unroll
    for (int mi = 0; mi < 4; mi++) {
        float s0 = 0.f, s1 = 0.f;
        #pragma unroll
        for (int ni = 0; ni < 8; ni++) {
            int c = nBase + ni * 8 + t * 2;
            s0 += fmaxf(acc[mi][ni][0] + b1s[c],     0.f) * w2s[c]
                + fmaxf(acc[mi][ni][1] + b1s[c + 1], 0.f) * w2s[c + 1];
            s1 += fmaxf(acc[mi][ni][2] + b1s[c],     0.f) * w2s[c]
                + fmaxf(acc[mi][ni][3] + b1s[c + 1], 0.f) * w2s[c + 1];
        }
        s0 += __shfl_xor_sync(0xffffffff, s0, 1); s0 += __shfl_xor_sync(0xffffffff, s0, 2);
        s1 += __shfl_xor_sync(0xffffffff, s1, 1); s1 += __shfl_xor_sync(0xffffffff, s1, 2);
        if (t == 0) {
            atomicAdd(&s_part[mBase + mi * 16 + g],     s0);
            atomicAdd(&s_part[mBase + mi * 16 + 8 + g], s1);
        }
    }
    __syncthreads();
    if (tid < 128) atomicAdd(&g_att[rowBase + tid], s_part[tid]);
}

// ===========================================================================
// k_stats4: per-batch softmax/moments/r/w, then h-sliced context stream.
// ===========================================================================
__global__ __launch_bounds__(256)
void k_stats4(const float* __restrict__ x,
              const unsigned char* __restrict__ mask,
              const float* __restrict__ G,
              const float* __restrict__ mub) {
    __shared__ float smax[8], ssum[8][6];
    __shared__ float r_s[NB], w_s[SEQ];
    __shared__ float4 red[256];

    const int b = blockIdx.y, slice = blockIdx.x;
    const int tid = threadIdx.x, lane = tid & 31, warp = tid >> 5;

    float logit = -3.0e38f;
    if (tid < SEQ) {
        logit = g_att[b * SEQ + tid];
        if (mask[b * SEQ + tid]) logit = -1.0e9f;
    }
    float v = logit;
    #pragma unroll
    for (int off = 16; off > 0; off >>= 1) v = fmaxf(v, __shfl_xor_sync(0xffffffff, v, off));
    if (lane == 0) smax[warp] = v;
    __syncthreads();
    float mx = smax[0];
    #pragma unroll
    for (int w = 1; w < 8; w++) mx = fmaxf(mx, smax[w]);

    float e = (tid < SEQ) ? expf(logit - mx) : 0.f;
    float px = 0.f, py = 0.f;
    if (tid < SEQ) { px = (float)(tid / 14) * (1.f / 13.f); py = (float)(tid % 14) * (1.f / 13.f); }
    float s6[6] = { e, e * px, e * py, e * px * px, e * px * py, e * py * py };
    #pragma unroll
    for (int q = 0; q < 6; q++) {
        float sv = s6[q];
        #pragma unroll
        for (int off = 16; off > 0; off >>= 1) sv += __shfl_xor_sync(0xffffffff, sv, off);
        if (lane == 0) ssum[warp][q] = sv;
    }
    __syncthreads();
    float sums[6];
    #pragma unroll
    for (int q = 0; q < 6; q++) {
        float sv = 0.f;
        #pragma unroll
        for (int w = 0; w < 8; w++) sv += ssum[w][q];
        sums[q] = sv;
    }

    const float S   = sums[0];
    const float Mux = sums[1] / S, Muy = sums[2] / S;
    float S00 = sums[3] / S - Mux * Mux + 1e-6f;
    float S01 = sums[4] / S - Mux * Muy;
    float S11 = sums[5] / S - Muy * Muy + 1e-6f;
    float det = S00 * S11 - S01 * S01;
    float I00 = S11 / det, I01 = -S01 / det, I11 = S00 / det;
    float t0 = I00 * Mux + I01 * Muy;
    float t1 = I01 * Mux + I11 * Muy;
    float ds = I00 * I11 - I01 * I01;
    float R00 = I11 / ds, R01 = -I01 / ds, R11 = I00 / ds;
    float m0 = R00 * t0 + R01 * t1;
    float m1 = R01 * t0 + R11 * t1;
    float A00 = R00 + 1e-3f, A01 = R01, A11 = R11 + 1e-3f;
    float detA = A00 * A11 - A01 * A01;
    float Ai00 = A11 / detA, Ai01 = -A01 / detA, Ai11 = A00 / detA;
    float coef = 1.f / (6.2831853071795864769f * sqrtf(detA));

    if (tid < NB) {
        float d0 = m0 - mub[2 * tid];
        float d1 = m1 - mub[2 * tid + 1];
        float quad = d0 * (Ai00 * d0 + Ai01 * d1) + d1 * (Ai01 * d0 + Ai11 * d1);
        r_s[tid] = expf(-0.5f * quad) * coef;
    }
    __syncthreads();
    if (tid < SEQ) {
        float wv = 0.f;
        #pragma unroll 4
        for (int k = 0; k < NB; k++) wv += G[tid * NB + k] * r_s[k];
        w_s[tid] = wv;
    }
    __syncthreads();

    const int h4 = tid & 63, nn = tid >> 6;
    const float4* xb = (const float4*)(x + (size_t)b * SEQ * HID) + slice * 64 + h4;
    float ax = 0.f, ay = 0.f, az = 0.f, aw = 0.f;
    #pragma unroll 7
    for (int n = nn; n < SEQ; n += 4) {
        float4 vv = xb[n * 256];
        float wv = w_s[n];
        ax += wv * vv.x; ay += wv * vv.y; az += wv * vv.z; aw += wv * vv.w;
    }
    red[tid] = make_float4(ax, ay, az, aw);
    __syncthreads();
    if (tid < 64) {
        float4 a0 = red[tid], a1 = red[tid + 64], a2 = red[tid + 128], a3 = red[tid + 192];
        float4 o;
        o.x = a0.x + a1.x + a2.x + a3.x;
        o.y = a0.y + a1.y + a2.y + a3.y;
        o.z = a0.z + a1.z + a2.z + a3.z;
        o.w = a0.w + a1.w + a2.w + a3.w;
        ((float4*)(g_ctx + (size_t)b * HID + slice * 256))[tid] = o;
    }
}

// ===========================================================================
// k_out2: out = ctx(512x1024) @ Wm^T + bm  (tf32 mma.sync, BM=64 BN=128)
// ===========================================================================
#define BM2 64
#define BN2 128
#define XS2 20

__global__ __launch_bounds__(256, 2)
void k_out2(const float* __restrict__ Wm, const float* __restrict__ bm,
            float* __restrict__ out) {
    __shared__ unsigned sa[2][BM2][XS2];
    __shared__ unsigned sbm[2][BN2][XS2];

    const int tid = threadIdx.x;
    const int mB = blockIdx.x * BM2, nB = blockIdx.y * BN2;
    const int lr = tid >> 2, lc = (tid & 3) * 4;
    const int warp = tid >> 5, lane = tid & 31;
    const int wm = warp & 1, wn = warp >> 1;
    const int mBase = wm * 32, nBase = wn * 32;
    const int g = lane >> 2, t = lane & 3;

    float acc[2][4][4];
    #pragma unroll
    for (int mi = 0; mi < 2; mi++)
        #pragma unroll
        for (int ni = 0; ni < 4; ni++)
            #pragma unroll
            for (int q = 0; q < 4; q++) acc[mi][ni][q] = 0.f;

    float4 pa, pb0, pb1;
    pa  = *(const float4*)&g_ctx[(size_t)(mB + lr) * HID + lc];
    pb0 = *(const float4*)&Wm  [(size_t)(nB + lr) * HID + lc];
    pb1 = *(const float4*)&Wm  [(size_t)(nB + lr + 64) * HID + lc];
    sa [0][lr][lc+0] = f2tf32(pa.x);  sa [0][lr][lc+1] = f2tf32(pa.y);
    sa [0][lr][lc+2] = f2tf32(pa.z);  sa [0][lr][lc+3] = f2tf32(pa.w);
    sbm[0][lr][lc+0] = f2tf32(pb0.x); sbm[0][lr][lc+1] = f2tf32(pb0.y);
    sbm[0][lr][lc+2] = f2tf32(pb0.z); sbm[0][lr][lc+3] = f2tf32(pb0.w);
    sbm[0][lr+64][lc+0] = f2tf32(pb1.x); sbm[0][lr+64][lc+1] = f2tf32(pb1.y);
    sbm[0][lr+64][lc+2] = f2tf32(pb1.z); sbm[0][lr+64][lc+3] = f2tf32(pb1.w);
    __syncthreads();

    const int NT = HID / 16;
    for (int kt = 0; kt < NT; ++kt) {
        const int buf = kt & 1;
        if (kt < NT - 1) {
            int k0 = (kt + 1) * 16;
            pa  = *(const float4*)&g_ctx[(size_t)(mB + lr) * HID + k0 + lc];
            pb0 = *(const float4*)&Wm  [(size_t)(nB + lr) * HID + k0 + lc];
            pb1 = *(const float4*)&Wm  [(size_t)(nB + lr + 64) * HID + k0 + lc];
        }
        #pragma unroll
        for (int ks = 0; ks < 2; ++ks) {
            const int k0s = ks * 8;
            unsigned a[2][4], bf[4][2];
            #pragma unroll
            for (int mi = 0; mi < 2; mi++) {
                int r0 = mBase + mi * 16 + g;
                a[mi][0] = sa[buf][r0    ][k0s + t];
                a[mi][1] = sa[buf][r0 + 8][k0s + t];
                a[mi][2] = sa[buf][r0    ][k0s + t + 4];
                a[mi][3] = sa[buf][r0 + 8][k0s + t + 4];
            }
            #pragma unroll
            for (int ni = 0; ni < 4; ni++) {
                int c0 = nBase + ni * 8 + g;
                bf[ni][0] = sbm[buf][c0][k0s + t];
                bf[ni][1] = sbm[buf][c0][k0s + t + 4];
            }
            #pragma unroll
            for (int mi = 0; mi < 2; mi++)
                #pragma unroll
                for (int ni = 0; ni < 4; ni++)
                    asm volatile(
                        "mma.sync.aligned.m16n8k8.row.col.f32.tf32.tf32.f32 "
                        "{%0,%1,%2,%3},{%4,%5,%6,%7},{%8,%9},{%0,%1,%2,%3};"
                        : "+f"(acc[mi][ni][0]), "+f"(acc[mi][ni][1]),
                          "+f"(acc[mi][ni][2]), "+f"(acc[mi][ni][3])
                        : "r"(a[mi][0]), "r"(a[mi][1]), "r"(a[mi][2]), "r"(a[mi][3]),
                          "r"(bf[ni][0]), "r"(bf[ni][1]));
        }
        if (kt < NT - 1) {
            int nb = buf ^ 1;
            sa [nb][lr][lc+0] = f2tf32(pa.x);  sa [nb][lr][lc+1] = f2tf32(pa.y);
            sa [nb][lr][lc+2] = f2tf32(pa.z);  sa [nb][lr][lc+3] = f2tf32(pa.w);
            sbm[nb][lr][lc+0] = f2tf32(pb0.x); sbm[nb][lr][lc+1] = f2tf32(pb0.y);
            sbm[nb][lr][lc+2] = f2tf32(pb0.z); sbm[nb][lr][lc+3] = f2tf32(pb0.w);
            sbm[nb][lr+64][lc+0] = f2tf32(pb1.x); sbm[nb][lr+64][lc+1] = f2tf32(pb1.y);
            sbm[nb][lr+64][lc+2] = f2tf32(pb1.z); sbm[nb][lr+64][lc+3] = f2tf32(pb1.w);
        }
        __syncthreads();
    }

    #pragma unroll
    for (int mi = 0; mi < 2; mi++)
        #pragma unroll
        for (int ni = 0; ni < 4; ni++) {
            int r0 = mB + mBase + mi * 16 + g;
            int c0 = nB + nBase + ni * 8 + t * 2;
            float bm0 = bm[c0], bm1 = bm[c0 + 1];
            out[(size_t)r0 * FOUT + c0]           = acc[mi][ni][0] + bm0;
            out[(size_t)r0 * FOUT + c0 + 1]       = acc[mi][ni][1] + bm1;
            out[(size_t)(r0 + 8) * FOUT + c0]     = acc[mi][ni][2] + bm0;
            out[(size_t)(r0 + 8) * FOUT + c0 + 1] = acc[mi][ni][3] + bm1;
        }
}

// ---------------------------------------------------------------------------
extern "C" void kernel_launch(void* const* d_in, const int* in_sizes, int n_in,
                              void* d_out, int out_size) {
    const float*         x   = (const float*)d_in[0];
    const unsigned char* xm  = (const unsigned char*)d_in[1];
    const float*         W1  = (const float*)d_in[2];
    const float*         b1  = (const float*)d_in[3];
    const float*         W2  = (const float*)d_in[4];
    // d_in[5] = b2: softmax-invariant
    const float*         Wm  = (const float*)d_in[6];
    const float*         bm  = (const float*)d_in[7];
    const float*         G   = (const float*)d_in[8];
    const float*         mub = (const float*)d_in[9];
    float* out = (float*)d_out;

    cudaFuncSetAttribute(k_mlp_att, cudaFuncAttributeMaxDynamicSharedMemorySize, GEMM_SMEM);

    k_pre<<<610, 256>>>(W1);                                   // 131072 + 25088 tasks
    k_mlp_att<<<dim3(2, ROWS / 128), 256, GEMM_SMEM>>>(x, b1, W2);
    k_stats4<<<dim3(4, BATCH), 256>>>(x, xm, G, mub);
    k_out2<<<dim3(BATCH / BM2, FOUT / BN2), 256>>>(Wm, bm, out);
}